// round 9
// baseline (speedup 1.0000x reference)
#include <cuda_runtime.h>

// ComNet: R=64 runs, T=256 timesteps, N=1024 agents, MLP 4->10(tanh)->2.
// Warp-autonomous strips: warp w owns timesteps [32w, 32w+32) and runs its own
// private 318-step wavefront (skew 2 per lane, B=4 agent blocks). Inter-warp
// dependency = completed comm row c(32w-1, .), streamed by warp w-1 lane31
// into a write-once smem row buffer with a release-published progress counter;
// warp w lane0 acquire-polls with a cached counter + nanosleep backoff.
// NO __syncthreads in the main loop.

#define R_  64
#define T_  256
#define N_  1024
#define NB_ 256            // agent blocks per row (N/4)
#define LSTEP_ 318         // 2*31 + 256 warp-local steps

__device__ __forceinline__ float htanh(float x) {
    float r; asm("tanh.approx.f32 %0, %1;" : "=f"(r) : "f"(x)); return r;
}

__global__ __launch_bounds__(256, 1)
void comnet_kernel(const float* __restrict__ runs,
                   const float* __restrict__ comm0,
                   const float* __restrict__ w1,
                   const float* __restrict__ b1,
                   const float* __restrict__ w2,
                   const float* __restrict__ b2,
                   float* __restrict__ out)
{
    // boundary comm rows: warp w-1 writes rows4[w-1][0..255], warp w reads
    __shared__ float4 rows4[7][NB_];
    __shared__ int    cnt[7];          // blocks completed per boundary row

    const int r    = blockIdx.x;
    const int t    = threadIdx.x;      // global timestep role
    const int lane = t & 31;           // skew 2*lane within the strip
    const int warp = t >> 5;

    if (t < 7) cnt[t] = 0;
    __syncthreads();                   // only barrier (init visibility)

    const unsigned cnt_prev = (warp > 0)
        ? (unsigned)__cvta_generic_to_shared(&cnt[warp - 1]) : 0u;
    const unsigned cnt_me   = (warp < 7)
        ? (unsigned)__cvta_generic_to_shared(&cnt[warp]) : 0u;
    const float* rowf_prev = (warp > 0) ? (const float*)rows4[warp - 1]
                                        : (const float*)rows4[0];

    // ---- weights in registers ----
    float W1[40], B1[10], W2[20];
#pragma unroll
    for (int k = 0; k < 40; ++k) W1[k] = w1[k];
#pragma unroll
    for (int k = 0; k < 10; ++k) B1[k] = b1[k];
#pragma unroll
    for (int k = 0; k < 20; ++k) W2[k] = w2[k];
    const float B2lo = b2[0];
    const float B2hi = b2[1];

    const float4* __restrict__ xrow4 =
        (const float4*)(runs + ((size_t)r * T_ + t) * (size_t)N_ * 2);
    float4* __restrict__ orow4 = (float4*)(out + ((size_t)r * T_ + t) * N_);
    const float* __restrict__ c0row = comm0 + (size_t)r * N_;

    float4 h1 = make_float4(0.f, 0.f, 0.f, 0.f);   // own block @ local s-1
    float4 h2 = h1;                                // own block @ local s-2

    // prefetch block 0 inputs (every thread eventually processes b=0)
    float4 px0 = xrow4[0];
    float4 px1 = xrow4[1];
    float4 pc0 = h1;
    if (t == 0) pc0 = make_float4(c0row[1], c0row[2], c0row[3], c0row[4]);

    int seen = 0;                      // cached progress of previous boundary

    for (int s = 0; s < LSTEP_; ++s) {
        const int b = s - 2 * lane;
        const bool active = ((unsigned)b < (unsigned)NB_);

        // ---- lane0 waits (cached fast path; nanosleep backoff on miss) ----
        if (lane == 0 && warp > 0 && active) {
            const int need = (b + 2 < NB_) ? (b + 2) : NB_;
            if (seen < need) {
                for (;;) {
                    asm volatile("ld.acquire.cta.shared.b32 %0, [%1];"
                                 : "=r"(seen) : "r"(cnt_prev) : "memory");
                    if (seen >= need) break;
                    __nanosleep(64);
                }
            }
        }

        // ---- right values c(t-1, 4b+1..4b+4): intra-warp via shuffles ----
        float r0 = __shfl_up_sync(0xffffffffu, h2.y, 1);
        float r1 = __shfl_up_sync(0xffffffffu, h2.z, 1);
        float r2 = __shfl_up_sync(0xffffffffu, h2.w, 1);
        float r3 = __shfl_up_sync(0xffffffffu, h1.x, 1);
        if (lane == 0) {
            if (warp > 0) {
                if (active) {
                    const float4 g = rows4[warp - 1][b];
                    r0 = g.y; r1 = g.z; r2 = g.w;
                    r3 = (b < NB_ - 1) ? rowf_prev[4 * b + 4] : 0.0f;
                }
            } else {   // t == 0: initial comm row
                r0 = pc0.x; r1 = pc0.y; r2 = pc0.z; r3 = pc0.w;
            }
        }
        if (b == NB_ - 1) r3 = 0.0f;   // zero right boundary for agent N-1

        const float4 cx0 = px0, cx1 = px1;

        // ---- prefetch next step's block inputs ----
        const int bn = s + 1 - 2 * lane;
        if ((unsigned)bn < (unsigned)NB_) {
            px0 = xrow4[2 * bn];
            px1 = xrow4[2 * bn + 1];
            if (t == 0) {
                const int base = 4 * bn;
                pc0 = make_float4(c0row[base + 1], c0row[base + 2],
                                  c0row[base + 3],
                                  (bn < NB_ - 1) ? c0row[base + 4] : 0.0f);
            }
        }

        float4 cur = h1;
        if (active) {
            float o0v[4], o1v[4];
            float lf = (b == 0) ? 0.0f : h1.w;     // c(t, 4b-1)
#pragma unroll
            for (int k = 0; k < 4; ++k) {
                const float xx = (k == 0) ? cx0.x : (k == 1) ? cx0.z
                                : (k == 2) ? cx1.x : cx1.z;
                const float xy = (k == 0) ? cx0.y : (k == 1) ? cx0.w
                                : (k == 2) ? cx1.y : cx1.w;
                const float rt = (k == 0) ? r0 : (k == 1) ? r1
                                : (k == 2) ? r2 : r3;

                float a0 = B2lo, a0b = 0.f, a1 = B2hi, a1b = 0.f;
#pragma unroll
                for (int j = 0; j < 10; ++j) {
                    float a = fmaf(W1[4 * j + 0], xx, B1[j]);
                    a       = fmaf(W1[4 * j + 1], xy, a);
                    a       = fmaf(W1[4 * j + 3], rt, a);
                    a       = fmaf(W1[4 * j + 2], lf, a);   // lf last: shortest chain
                    const float h = htanh(a);               // MUFU.TANH
                    if (j & 1) { a0b = fmaf(W2[j], h, a0b); a1b = fmaf(W2[10 + j], h, a1b); }
                    else       { a0  = fmaf(W2[j], h, a0);  a1  = fmaf(W2[10 + j], h, a1); }
                }
                o0v[k] = a0 + a0b;
                const float o1 = a1 + a1b;
                o1v[k] = o1;
                lf = o1;                           // left-chain within block
            }
            orow4[b] = make_float4(o0v[0], o0v[1], o0v[2], o0v[3]);
            cur = make_float4(o1v[0], o1v[1], o1v[2], o1v[3]);

            // ---- lane31 publishes its comm block for the next warp ----
            if (lane == 31 && warp < 7) {
                rows4[warp][b] = cur;              // STS.128 (write-once slot)
                asm volatile("st.release.cta.shared.b32 [%0], %1;"
                             :: "r"(cnt_me), "r"(b + 1) : "memory");
            }
        }

        h2 = h1;
        if (active) h1 = cur;
    }
}

extern "C" void kernel_launch(void* const* d_in, const int* in_sizes, int n_in,
                              void* d_out, int out_size)
{
    const float* runs  = (const float*)d_in[0];
    const float* comm0 = (const float*)d_in[1];
    const float* w1    = (const float*)d_in[2];
    const float* b1    = (const float*)d_in[3];
    const float* w2    = (const float*)d_in[4];
    const float* b2    = (const float*)d_in[5];
    float* out = (float*)d_out;

    comnet_kernel<<<R_, T_>>>(runs, comm0, w1, b1, w2, b2, out);
}